// round 16
// baseline (speedup 1.0000x reference)
#include <cuda_runtime.h>

#define T_STEPS 2048
#define BATCH   2048
#define HID     32
#define NTHD    320
#define NCTA    148

typedef unsigned long long u64;

#define S_SIG  (-1.4426950408889634f)   /* -log2(e)   */
#define S_TNH  (-2.8853900817779268f)   /* -2*log2(e) */

// ---- packed f32x2 helpers ----
__device__ __forceinline__ u64 ffma2(u64 a, u64 b, u64 c) {
    u64 d;
    asm("fma.rn.f32x2 %0, %1, %2, %3;" : "=l"(d) : "l"(a), "l"(b), "l"(c));
    return d;
}
__device__ __forceinline__ u64 pack2(float lo, float hi) {
    u64 d;
    asm("mov.b64 %0, {%1, %2};" : "=l"(d) : "f"(lo), "f"(hi));
    return d;
}
__device__ __forceinline__ void unpack2(u64 v, float& lo, float& hi) {
    asm("mov.b64 {%0, %1}, %2;" : "=f"(lo), "=f"(hi) : "l"(v));
}
__device__ __forceinline__ float ex2f(float x) {
    float y; asm("ex2.approx.f32 %0, %1;" : "=f"(y) : "f"(x)); return y;
}
__device__ __forceinline__ float rcpf(float x) {
    float y; asm("rcp.approx.f32 %0, %1;" : "=f"(y) : "f"(x)); return y;
}
__device__ __forceinline__ void stg64_pred(int pred, float* p, float a, float b) {
    asm volatile("{\n\t"
                 ".reg .pred p;\n\t"
                 "setp.ne.u32 p, %0, 0;\n\t"
                 "@p st.global.v2.f32 [%1], {%2, %3};\n\t"
                 "}" :: "r"(pred), "l"(p), "f"(a), "f"(b) : "memory");
}
__device__ __forceinline__ void stg32_pred(int pred, float* p, float a) {
    asm volatile("{\n\t"
                 ".reg .pred p;\n\t"
                 "setp.ne.u32 p, %0, 0;\n\t"
                 "@p st.global.f32 [%1], %2;\n\t"
                 "}" :: "r"(pred), "l"(p), "f"(a) : "memory");
}

__global__ void __launch_bounds__(NTHD, 1) lstm_kernel(
    const float* __restrict__ x,      // [T, B, 1]
    const float* __restrict__ W_ih,   // [4H, 1]
    const float* __restrict__ W_hh,   // [4H, H]
    const float* __restrict__ b_ih,   // [4H]
    const float* __restrict__ b_hh,   // [4H]
    const float* __restrict__ W_out,  // [1, H]
    const float* __restrict__ b_out,  // [1]
    float* __restrict__ out,          // [T*B] outs, then [B*H] hT, then [B*H] cT
    int out_size)
{
    const int lane = threadIdx.x & 31;
    const int wid  = threadIdx.x >> 5;

    // wid 6..9: HEAVY (2 batches), one per SMSP, HIGH wid -> arbiter priority.
    // wid 0..5: LIGHT (1 batch).
    const bool heavy = (wid >= 6);

    const float wout = W_out[lane];
    const float bout = b_out[0];
    const bool has_state = (out_size >= T_STEPS * BATCH + 2 * BATCH * HID);
    float* hT = out + (size_t)T_STEPS * BATCH;
    float* cT = hT + BATCH * HID;

    // h staging (per-warp slots, no cross-warp sharing)
    __shared__ __align__(16) float shh[4][2][2][32];   // heavy: [hp][buf][batch][lane]
    __shared__ __align__(16) float shl[6][2][32];      // light: [wid][buf][lane]

    if (heavy) {
        // ===================== HEAVY: 2 batches (R5 body) =====================
        const int hp = wid - 6;
        const int b0 = 2 * (blockIdx.x * 4 + hp);      // 0..1182

        u64 w2[4][16];
        float wih[4], bias[4];
        #pragma unroll
        for (int g = 0; g < 4; g++) {
            const int row = g * 32 + lane;
            const float s = (g == 2) ? S_TNH : S_SIG;
            const float* wr = W_hh + row * HID;
            #pragma unroll
            for (int p = 0; p < 16; p++)
                w2[g][p] = pack2(wr[2 * p] * s, wr[2 * p + 1] * s);
            wih[g]  = W_ih[row] * s;
            bias[g] = (b_ih[row] + b_hh[row]) * s;
        }

        float h0 = 0.f, c0 = 0.f, h1 = 0.f, c1 = 0.f;
        float rp0 = 0.f, rp1 = 0.f;

        const float* xp = x + b0;
        float2 xv = *reinterpret_cast<const float2*>(xp);
        float* outp = out + b0;
        const int store_pred = (lane == 0);

        #pragma unroll 2
        for (int t = 0; t < T_STEPS; t++) {
            const int buf = t & 1;
            shh[hp][buf][0][lane] = h0;
            shh[hp][buf][1][lane] = h1;

            const float* xpn = (t < T_STEPS - 1) ? (xp + BATCH) : xp;
            float2 xnext = *reinterpret_cast<const float2*>(xpn);
            xp = xpn;

            u64 acc0[4], acc1[4];
            #pragma unroll
            for (int g = 0; g < 4; g++) {
                acc0[g] = pack2(fmaf(xv.x, wih[g], bias[g]), 0.0f);
                acc1[g] = pack2(fmaf(xv.y, wih[g], bias[g]), 0.0f);
            }

            __syncwarp();

            float r0 = rp0, r1 = rp1;
            #pragma unroll
            for (int off = 16; off; off >>= 1) {
                r0 += __shfl_xor_sync(0xffffffffu, r0, off);
                r1 += __shfl_xor_sync(0xffffffffu, r1, off);
            }

            const double2* hp0 = reinterpret_cast<const double2*>(shh[hp][buf][0]);
            const double2* hp1 = reinterpret_cast<const double2*>(shh[hp][buf][1]);
            #pragma unroll
            for (int q = 0; q < 8; q++) {
                double2 v0 = hp0[q], v1 = hp1[q];
                u64 p00 = __double_as_longlong(v0.x), p01 = __double_as_longlong(v0.y);
                u64 p10 = __double_as_longlong(v1.x), p11 = __double_as_longlong(v1.y);
                #pragma unroll
                for (int g = 0; g < 4; g++) {
                    acc0[g] = ffma2(p00, w2[g][2 * q], acc0[g]);
                    acc1[g] = ffma2(p10, w2[g][2 * q], acc1[g]);
                }
                #pragma unroll
                for (int g = 0; g < 4; g++) {
                    acc0[g] = ffma2(p01, w2[g][2 * q + 1], acc0[g]);
                    acc1[g] = ffma2(p11, w2[g][2 * q + 1], acc1[g]);
                }
            }

            stg64_pred(store_pred, outp, r0 + bout, r1 + bout);
            outp += (t > 0) ? BATCH : 0;

            float vi0, vf0, vg0, vo0, vi1, vf1, vg1, vo1;
            {
                float lo, hi;
                unpack2(acc0[0], lo, hi); vi0 = lo + hi;
                unpack2(acc0[1], lo, hi); vf0 = lo + hi;
                unpack2(acc0[2], lo, hi); vg0 = lo + hi;
                unpack2(acc0[3], lo, hi); vo0 = lo + hi;
                unpack2(acc1[0], lo, hi); vi1 = lo + hi;
                unpack2(acc1[1], lo, hi); vf1 = lo + hi;
                unpack2(acc1[2], lo, hi); vg1 = lo + hi;
                unpack2(acc1[3], lo, hi); vo1 = lo + hi;
            }

            float i0g, f0g, o0g, g0g;
            {
                float Ei = ex2f(vi0), Ef = ex2f(vf0), Eg = ex2f(vg0), Eo = ex2f(vo0);
                float Pi = 1.f + Ei, Pf = 1.f + Ef, Pg = 1.f + Eg, Po = 1.f + Eo;
                float Pif = Pi * Pf, Pgo = Pg * Po;
                float R = rcpf(Pif * Pgo);
                float PgoR = Pgo * R, PifR = Pif * R;
                i0g = Pf * PgoR; f0g = Pi * PgoR;
                o0g = PifR * Pg; g0g = fmaf(2.f, PifR * Po, -1.f);
            }
            float i1g, f1g, o1g, g1g;
            {
                float Ei = ex2f(vi1), Ef = ex2f(vf1), Eg = ex2f(vg1), Eo = ex2f(vo1);
                float Pi = 1.f + Ei, Pf = 1.f + Ef, Pg = 1.f + Eg, Po = 1.f + Eo;
                float Pif = Pi * Pf, Pgo = Pg * Po;
                float R = rcpf(Pif * Pgo);
                float PgoR = Pgo * R, PifR = Pif * R;
                i1g = Pf * PgoR; f1g = Pi * PgoR;
                o1g = PifR * Pg; g1g = fmaf(2.f, PifR * Po, -1.f);
            }

            c0 = fmaf(f0g, c0, i0g * g0g);
            c1 = fmaf(f1g, c1, i1g * g1g);

            {
                float a0 = fminf(c0 * S_TNH, 63.f);
                float a1 = fminf(c1 * S_TNH, 63.f);
                float T0 = 1.f + ex2f(a0);
                float T1 = 1.f + ex2f(a1);
                float Rt = rcpf(T0 * T1);
                h0 = o0g * fmaf(2.f, T1 * Rt, -1.f);
                h1 = o1g * fmaf(2.f, T0 * Rt, -1.f);
            }

            rp0 = h0 * wout;
            rp1 = h1 * wout;
            xv = xnext;
        }

        {
            float r0 = rp0, r1 = rp1;
            #pragma unroll
            for (int off = 16; off; off >>= 1) {
                r0 += __shfl_xor_sync(0xffffffffu, r0, off);
                r1 += __shfl_xor_sync(0xffffffffu, r1, off);
            }
            stg64_pred(store_pred, outp, r0 + bout, r1 + bout);
        }
        if (has_state) {
            hT[(size_t)(b0 + 0) * HID + lane] = h0;
            hT[(size_t)(b0 + 1) * HID + lane] = h1;
            cT[(size_t)(b0 + 0) * HID + lane] = c0;
            cT[(size_t)(b0 + 1) * HID + lane] = c1;
        }
    } else {
        // ===================== LIGHT: 1 batch =====================
        const int b = 1184 + blockIdx.x * 6 + wid;     // 1184..2071
        if (b >= BATCH) return;                        // 24 invalid slots exit

        u64 w2[4][16];
        float wih[4], bias[4];
        #pragma unroll
        for (int g = 0; g < 4; g++) {
            const int row = g * 32 + lane;
            const float s = (g == 2) ? S_TNH : S_SIG;
            const float* wr = W_hh + row * HID;
            #pragma unroll
            for (int p = 0; p < 16; p++)
                w2[g][p] = pack2(wr[2 * p] * s, wr[2 * p + 1] * s);
            wih[g]  = W_ih[row] * s;
            bias[g] = (b_ih[row] + b_hh[row]) * s;
        }

        float h0 = 0.f, c0 = 0.f, rp0 = 0.f;

        const float* xp = x + b;
        float xv = *xp;
        float* outp = out + b;
        const int store_pred = (lane == 0);

        #pragma unroll 2
        for (int t = 0; t < T_STEPS; t++) {
            const int buf = t & 1;
            shl[wid][buf][lane] = h0;

            const float* xpn = (t < T_STEPS - 1) ? (xp + BATCH) : xp;
            float xnext = *xpn;
            xp = xpn;

            u64 acc0[4];
            #pragma unroll
            for (int g = 0; g < 4; g++)
                acc0[g] = pack2(fmaf(xv, wih[g], bias[g]), 0.0f);

            __syncwarp();

            float r0 = rp0;
            #pragma unroll
            for (int off = 16; off; off >>= 1)
                r0 += __shfl_xor_sync(0xffffffffu, r0, off);

            const double2* hp0 = reinterpret_cast<const double2*>(shl[wid][buf]);
            #pragma unroll
            for (int q = 0; q < 8; q++) {
                double2 v0 = hp0[q];
                u64 p00 = __double_as_longlong(v0.x), p01 = __double_as_longlong(v0.y);
                #pragma unroll
                for (int g = 0; g < 4; g++)
                    acc0[g] = ffma2(p00, w2[g][2 * q], acc0[g]);
                #pragma unroll
                for (int g = 0; g < 4; g++)
                    acc0[g] = ffma2(p01, w2[g][2 * q + 1], acc0[g]);
            }

            stg32_pred(store_pred, outp, r0 + bout);
            outp += (t > 0) ? BATCH : 0;

            float vi0, vf0, vg0, vo0;
            {
                float lo, hi;
                unpack2(acc0[0], lo, hi); vi0 = lo + hi;
                unpack2(acc0[1], lo, hi); vf0 = lo + hi;
                unpack2(acc0[2], lo, hi); vg0 = lo + hi;
                unpack2(acc0[3], lo, hi); vo0 = lo + hi;
            }
            float i0g, f0g, o0g, g0g;
            {
                float Ei = ex2f(vi0), Ef = ex2f(vf0), Eg = ex2f(vg0), Eo = ex2f(vo0);
                float Pi = 1.f + Ei, Pf = 1.f + Ef, Pg = 1.f + Eg, Po = 1.f + Eo;
                float Pif = Pi * Pf, Pgo = Pg * Po;
                float R = rcpf(Pif * Pgo);
                float PgoR = Pgo * R, PifR = Pif * R;
                i0g = Pf * PgoR; f0g = Pi * PgoR;
                o0g = PifR * Pg; g0g = fmaf(2.f, PifR * Po, -1.f);
            }
            c0 = fmaf(f0g, c0, i0g * g0g);
            {
                float a0 = fminf(c0 * S_TNH, 63.f);
                float T0 = 1.f + ex2f(a0);
                h0 = o0g * fmaf(2.f, rcpf(T0), -1.f);
            }
            rp0 = h0 * wout;
            xv = xnext;
        }

        {
            float r0 = rp0;
            #pragma unroll
            for (int off = 16; off; off >>= 1)
                r0 += __shfl_xor_sync(0xffffffffu, r0, off);
            stg32_pred(store_pred, outp, r0 + bout);
        }
        if (has_state) {
            hT[(size_t)b * HID + lane] = h0;
            cT[(size_t)b * HID + lane] = c0;
        }
    }
}

extern "C" void kernel_launch(void* const* d_in, const int* in_sizes, int n_in,
                              void* d_out, int out_size) {
    const float* x     = (const float*)d_in[0];
    const float* W_ih  = (const float*)d_in[1];
    const float* W_hh  = (const float*)d_in[2];
    const float* b_ih  = (const float*)d_in[3];
    const float* b_hh  = (const float*)d_in[4];
    const float* W_out = (const float*)d_in[5];
    const float* b_out = (const float*)d_in[6];
    float* out = (float*)d_out;

    // 148 uniform CTAs x 320 threads: per CTA 4 heavy warps (wid 6..9, one per
    // SMSP, high-wid priority) + 6 light warps (wid 0..5). 1184 heavy batches +
    // 864 light batches = 2048; all-register weights; 3 streams on 4-batch SMSPs.
    lstm_kernel<<<NCTA, NTHD>>>(x, W_ih, W_hh, b_ih, b_hh, W_out, b_out, out, out_size);
}

// round 17
// speedup vs baseline: 1.3391x; 1.3391x over previous
#include <cuda_runtime.h>

#define T_STEPS 2048
#define BATCH   2048
#define HID     32

typedef unsigned long long u64;

#define S_SIG  (-1.4426950408889634f)   /* -log2(e)   */
#define S_TNH  (-2.8853900817779268f)   /* -2*log2(e) */

// ---- packed f32x2 helpers ----
__device__ __forceinline__ u64 ffma2(u64 a, u64 b, u64 c) {
    u64 d;
    asm("fma.rn.f32x2 %0, %1, %2, %3;" : "=l"(d) : "l"(a), "l"(b), "l"(c));
    return d;
}
__device__ __forceinline__ u64 pack2(float lo, float hi) {
    u64 d;
    asm("mov.b64 %0, {%1, %2};" : "=l"(d) : "f"(lo), "f"(hi));
    return d;
}
__device__ __forceinline__ void unpack2(u64 v, float& lo, float& hi) {
    asm("mov.b64 {%0, %1}, %2;" : "=f"(lo), "=f"(hi) : "l"(v));
}
__device__ __forceinline__ float ex2f(float x) {
    float y; asm("ex2.approx.f32 %0, %1;" : "=f"(y) : "f"(x)); return y;
}
__device__ __forceinline__ float rcpf(float x) {
    float y; asm("rcp.approx.f32 %0, %1;" : "=f"(y) : "f"(x)); return y;
}
__device__ __forceinline__ void stg32_pred(int pred, float* p, float a) {
    asm volatile("{\n\t"
                 ".reg .pred p;\n\t"
                 "setp.ne.u32 p, %0, 0;\n\t"
                 "@p st.global.f32 [%1], %2;\n\t"
                 "}" :: "r"(pred), "l"(p), "f"(a) : "memory");
}

__global__ void __launch_bounds__(128, 2) lstm_kernel(
    const float* __restrict__ x,      // [T, B, 1]
    const float* __restrict__ W_ih,   // [4H, 1]
    const float* __restrict__ W_hh,   // [4H, H]
    const float* __restrict__ b_ih,   // [4H]
    const float* __restrict__ b_hh,   // [4H]
    const float* __restrict__ W_out,  // [1, H]
    const float* __restrict__ b_out,  // [1]
    float* __restrict__ out,          // [T*B] outs, then [B*H] hT, then [B*H] cT
    int out_size)
{
    const int lane = threadIdx.x & 31;
    const int wid  = threadIdx.x >> 5;
    const int w    = blockIdx.x * 4 + wid;   // 0..1023
    const int b0   = 2 * w;                  // batch pair (b0, b0+1)

    // Per-lane weights, pre-scaled per gate (i,f,o: S_SIG; g: S_TNH).
    u64 w2[4][16];
    float wih[4], bias[4];
    #pragma unroll
    for (int g = 0; g < 4; g++) {
        const int row = g * 32 + lane;
        const float s = (g == 2) ? S_TNH : S_SIG;
        const float* wr = W_hh + row * HID;
        #pragma unroll
        for (int p = 0; p < 16; p++)
            w2[g][p] = pack2(wr[2 * p] * s, wr[2 * p + 1] * s);
        wih[g]  = W_ih[row] * s;
        bias[g] = (b_ih[row] + b_hh[row]) * s;
    }
    const float wout = W_out[lane];
    const float bout = b_out[0];

    // h broadcast staging: [warp][double-buffer][batch][hidden]
    __shared__ __align__(16) float sh[4][2][2][32];

    float h0 = 0.f, c0 = 0.f, h1 = 0.f, c1 = 0.f;
    float rp0 = 0.f, rp1 = 0.f;               // deferred output partials

    const float* xp = x + b0;
    float2 xv = *reinterpret_cast<const float2*>(xp);
    float* outp = out + b0;
    // dual-store predicate: lane 0 stores batch b0, lane 16 stores batch b0+1
    const int dual_pred = ((lane & 15) == 0);
    const int dual_off  = lane >> 4;          // 0 for lane0, 1 for lane16

    // prologue: publish h(-1) = 0 into buffer 0
    sh[wid][0][0][lane] = 0.f;
    sh[wid][0][1][lane] = 0.f;
    __syncwarp();

    #pragma unroll 2
    for (int t = 0; t < T_STEPS; t++) {
        const int buf = t & 1;

        // clamped prefetch of next x
        const float* xpn = (t < T_STEPS - 1) ? (xp + BATCH) : xp;
        float2 xnext = *reinterpret_cast<const float2*>(xpn);
        xp = xpn;

        // init gate accumulators: lo = x*wih + bias, hi = 0
        u64 acc0[4], acc1[4];
        #pragma unroll
        for (int g = 0; g < 4; g++) {
            acc0[g] = pack2(fmaf(xv.x, wih[g], bias[g]), 0.0f);
            acc1[g] = pack2(fmaf(xv.y, wih[g], bias[g]), 0.0f);
        }

        // deferred 6-shfl dual reduction of step t-1 output partials
        // (hidden under the matvec below)
        float s0 = rp0 + __shfl_xor_sync(0xffffffffu, rp0, 16);
        float s1 = rp1 + __shfl_xor_sync(0xffffffffu, rp1, 16);
        float rr = (lane < 16) ? s0 : s1;
        #pragma unroll
        for (int off = 8; off; off >>= 1)
            rr += __shfl_xor_sync(0xffffffffu, rr, off);
        // lanes 0-15: sum(rp0); lanes 16-31: sum(rp1)

        // recurrent matvec: 8 chains (2 batches x 4 gates), 128 FFMA2
        const double2* hp0 = reinterpret_cast<const double2*>(sh[wid][buf][0]);
        const double2* hp1 = reinterpret_cast<const double2*>(sh[wid][buf][1]);
        #pragma unroll
        for (int q = 0; q < 8; q++) {
            double2 v0 = hp0[q], v1 = hp1[q];
            u64 p00 = __double_as_longlong(v0.x), p01 = __double_as_longlong(v0.y);
            u64 p10 = __double_as_longlong(v1.x), p11 = __double_as_longlong(v1.y);
            #pragma unroll
            for (int g = 0; g < 4; g++) {
                acc0[g] = ffma2(p00, w2[g][2 * q], acc0[g]);
                acc1[g] = ffma2(p10, w2[g][2 * q], acc1[g]);
            }
            #pragma unroll
            for (int g = 0; g < 4; g++) {
                acc0[g] = ffma2(p01, w2[g][2 * q + 1], acc0[g]);
                acc1[g] = ffma2(p11, w2[g][2 * q + 1], acc1[g]);
            }
        }

        // store out[t-1] from lanes 0 and 16 (placeholder at t==0, overwritten at t==1)
        stg32_pred(dual_pred, outp + dual_off, rr + bout);
        outp += (t > 0) ? BATCH : 0;

        // ---- horizontal adds ----
        float vi0, vf0, vg0, vo0, vi1, vf1, vg1, vo1;
        {
            float lo, hi;
            unpack2(acc0[0], lo, hi); vi0 = lo + hi;
            unpack2(acc0[1], lo, hi); vf0 = lo + hi;
            unpack2(acc0[2], lo, hi); vg0 = lo + hi;
            unpack2(acc0[3], lo, hi); vo0 = lo + hi;
            unpack2(acc1[0], lo, hi); vi1 = lo + hi;
            unpack2(acc1[1], lo, hi); vf1 = lo + hi;
            unpack2(acc1[2], lo, hi); vg1 = lo + hi;
            unpack2(acc1[3], lo, hi); vo1 = lo + hi;
        }

        // ---- quad-shared-rcp gates, batch 0 ----
        float i0g, f0g, o0g, g0g;
        {
            float Ei = ex2f(vi0), Ef = ex2f(vf0), Eg = ex2f(vg0), Eo = ex2f(vo0);
            float Pi = 1.f + Ei, Pf = 1.f + Ef, Pg = 1.f + Eg, Po = 1.f + Eo;
            float Pif = Pi * Pf, Pgo = Pg * Po;
            float R = rcpf(Pif * Pgo);
            float PgoR = Pgo * R, PifR = Pif * R;
            i0g = Pf * PgoR; f0g = Pi * PgoR;
            o0g = PifR * Pg; g0g = fmaf(2.f, PifR * Po, -1.f);
        }
        // ---- quad-shared-rcp gates, batch 1 ----
        float i1g, f1g, o1g, g1g;
        {
            float Ei = ex2f(vi1), Ef = ex2f(vf1), Eg = ex2f(vg1), Eo = ex2f(vo1);
            float Pi = 1.f + Ei, Pf = 1.f + Ef, Pg = 1.f + Eg, Po = 1.f + Eo;
            float Pif = Pi * Pf, Pgo = Pg * Po;
            float R = rcpf(Pif * Pgo);
            float PgoR = Pgo * R, PifR = Pif * R;
            i1g = Pf * PgoR; f1g = Pi * PgoR;
            o1g = PifR * Pg; g1g = fmaf(2.f, PifR * Po, -1.f);
        }

        c0 = fmaf(f0g, c0, i0g * g0g);
        c1 = fmaf(f1g, c1, i1g * g1g);

        // ---- paired tanh(c): one rcp for both batches ----
        {
            float a0 = fminf(c0 * S_TNH, 63.f);
            float a1 = fminf(c1 * S_TNH, 63.f);
            float T0 = 1.f + ex2f(a0);
            float T1 = 1.f + ex2f(a1);
            float Rt = rcpf(T0 * T1);
            h0 = o0g * fmaf(2.f, T1 * Rt, -1.f);
            h1 = o1g * fmaf(2.f, T0 * Rt, -1.f);
        }

        // publish h(t) for step t+1 (buffer buf^1); syncwarp closes the iteration
        sh[wid][buf ^ 1][0][lane] = h0;
        sh[wid][buf ^ 1][1][lane] = h1;

        rp0 = h0 * wout;
        rp1 = h1 * wout;
        xv = xnext;

        __syncwarp();
    }

    // epilogue: reduce final step partials -> out[T-1] (outp already at row T-1)
    {
        float s0 = rp0 + __shfl_xor_sync(0xffffffffu, rp0, 16);
        float s1 = rp1 + __shfl_xor_sync(0xffffffffu, rp1, 16);
        float rr = (lane < 16) ? s0 : s1;
        #pragma unroll
        for (int off = 8; off; off >>= 1)
            rr += __shfl_xor_sync(0xffffffffu, rr, off);
        stg32_pred(dual_pred, outp + dual_off, rr + bout);
    }

    // final state (hT, cT), each [B, H], appended after outs
    if (out_size >= T_STEPS * BATCH + 2 * BATCH * HID) {
        float* hT = out + (size_t)T_STEPS * BATCH;
        float* cT = hT + BATCH * HID;
        hT[(size_t)(b0 + 0) * HID + lane] = h0;
        hT[(size_t)(b0 + 1) * HID + lane] = h1;
        cT[(size_t)(b0 + 0) * HID + lane] = c0;
        cT[(size_t)(b0 + 1) * HID + lane] = c1;
    }
}

extern "C" void kernel_launch(void* const* d_in, const int* in_sizes, int n_in,
                              void* d_out, int out_size) {
    const float* x     = (const float*)d_in[0];
    const float* W_ih  = (const float*)d_in[1];
    const float* W_hh  = (const float*)d_in[2];
    const float* b_ih  = (const float*)d_in[3];
    const float* b_hh  = (const float*)d_in[4];
    const float* W_out = (const float*)d_in[5];
    const float* b_out = (const float*)d_in[6];
    float* out = (float*)d_out;

    // 1024 warps (2 batch elems each) = 256 CTAs of 128 threads, 2 CTA/SM
    lstm_kernel<<<256, 128>>>(x, W_ih, W_hh, b_ih, b_hh, W_out, b_out, out, out_size);
}